// round 13
// baseline (speedup 1.0000x reference)
#include <cuda_runtime.h>
#include <cuda.h>
#include <cstdint>
#include <math.h>

// ---------------------------------------------------------------------------
// ViT MHA B=8, S=1024, D=1024, H=16, hd=64 (fp32 in/out).
// R11 = R10 fixed: __device__ plane arrays are selected INSIDE device code
//       (R10 passed device symbols as host-side kernel args -> garbage ptrs).
//       Split-bf16 (hi/lo) everywhere; producers write pre-split operands.
// ---------------------------------------------------------------------------

#define NB_HEADS 16
#define HEAD_DIM 64
#define SEQ 1024
#define BATCH 8
#define DMODEL 1024
#define NTOK (BATCH * SEQ)                     // 8192

// bf16 hi/lo planes (uint16_t storage), 16B-aligned for cp.async/uint2
__device__ __align__(16) uint16_t g_xh[(size_t)NTOK * DMODEL];
__device__ __align__(16) uint16_t g_xl[(size_t)NTOK * DMODEL];
__device__ __align__(16) uint16_t g_wqkvTh[(size_t)3072 * 1024];
__device__ __align__(16) uint16_t g_wqkvTl[(size_t)3072 * 1024];
__device__ __align__(16) uint16_t g_wprojTh[(size_t)1024 * 1024];
__device__ __align__(16) uint16_t g_wprojTl[(size_t)1024 * 1024];
__device__ __align__(16) uint16_t g_qh[(size_t)NTOK * DMODEL];
__device__ __align__(16) uint16_t g_ql[(size_t)NTOK * DMODEL];
__device__ __align__(16) uint16_t g_kh[(size_t)NTOK * DMODEL];
__device__ __align__(16) uint16_t g_kl[(size_t)NTOK * DMODEL];
__device__ __align__(16) uint16_t g_vh[(size_t)NTOK * DMODEL];
__device__ __align__(16) uint16_t g_vl[(size_t)NTOK * DMODEL];
__device__ __align__(16) uint16_t g_oh[(size_t)NTOK * DMODEL];
__device__ __align__(16) uint16_t g_ol[(size_t)NTOK * DMODEL];

// ------------------------------ helpers ------------------------------------
__device__ __forceinline__ uint32_t smem_u32(const void* p) {
    uint32_t a;
    asm("{ .reg .u64 t; cvta.to.shared.u64 t, %1; cvt.u32.u64 %0, t; }"
        : "=r"(a) : "l"(p));
    return a;
}

__device__ __forceinline__ uint32_t packbf(float lo, float hi) {
    uint32_t r;
    asm("cvt.rn.bf16x2.f32 %0, %1, %2;" : "=r"(r) : "f"(hi), "f"(lo));
    return r;
}
__device__ __forceinline__ float bf_lo(uint32_t u) { return __uint_as_float(u << 16); }
__device__ __forceinline__ float bf_hi(uint32_t u) { return __uint_as_float(u & 0xffff0000u); }

__device__ __forceinline__ void cp_async16(uint32_t dst, const void* src) {
    asm volatile("cp.async.ca.shared.global [%0], [%1], 16;"
                 :: "r"(dst), "l"(src) : "memory");
}
__device__ __forceinline__ void cp_commit() {
    asm volatile("cp.async.commit_group;" ::: "memory");
}
__device__ __forceinline__ void cp_wait0() {
    asm volatile("cp.async.wait_group 0;" ::: "memory");
}

__device__ __forceinline__ void mma_bf16(float& c0, float& c1, float& c2, float& c3,
                                         uint32_t a0, uint32_t a1, uint32_t a2,
                                         uint32_t a3, uint32_t b0, uint32_t b1) {
    asm volatile(
        "mma.sync.aligned.m16n8k16.row.col.f32.bf16.bf16.f32 "
        "{%0,%1,%2,%3}, {%4,%5,%6,%7}, {%8,%9}, {%0,%1,%2,%3};"
        : "+f"(c0), "+f"(c1), "+f"(c2), "+f"(c3)
        : "r"(a0), "r"(a1), "r"(a2), "r"(a3), "r"(b0), "r"(b1));
}

__device__ __forceinline__ void ldsm_x4(uint32_t& r0, uint32_t& r1,
                                        uint32_t& r2, uint32_t& r3, uint32_t a) {
    asm volatile("ldmatrix.sync.aligned.m8n8.x4.shared.b16 {%0,%1,%2,%3}, [%4];"
                 : "=r"(r0), "=r"(r1), "=r"(r2), "=r"(r3) : "r"(a));
}
__device__ __forceinline__ void ldsm_x4_t(uint32_t& r0, uint32_t& r1,
                                          uint32_t& r2, uint32_t& r3, uint32_t a) {
    asm volatile("ldmatrix.sync.aligned.m8n8.x4.trans.shared.b16 {%0,%1,%2,%3}, [%4];"
                 : "=r"(r0), "=r"(r1), "=r"(r2), "=r"(r3) : "r"(a));
}

// ---------------------------------------------------------------------------
// Prep: split x (fp32) -> g_xh / g_xl.
// ---------------------------------------------------------------------------
__global__ __launch_bounds__(256) void split_fp32(const float* __restrict__ in,
                                                  int n4) {
    const int i = blockIdx.x * 256 + threadIdx.x;
    if (i < n4) {
        const float4 v = ((const float4*)in)[i];
        const uint32_t h01 = packbf(v.x, v.y), h23 = packbf(v.z, v.w);
        const uint32_t l01 = packbf(v.x - bf_lo(h01), v.y - bf_hi(h01));
        const uint32_t l23 = packbf(v.z - bf_lo(h23), v.w - bf_hi(h23));
        ((uint2*)g_xh)[i] = make_uint2(h01, h23);
        ((uint2*)g_xl)[i] = make_uint2(l01, l23);
    }
}

// ---------------------------------------------------------------------------
// Prep: transpose + split weights. in [1024][C] fp32 -> [C][1024] hi/lo.
// which: 0 -> g_wqkvT planes, 1 -> g_wprojT planes.
// ---------------------------------------------------------------------------
__global__ __launch_bounds__(256) void transpose_split(const float* __restrict__ in,
                                                       int C, int which) {
    __shared__ float t[32][33];
    uint16_t* oh = which ? g_wprojTh : g_wqkvTh;
    uint16_t* ol = which ? g_wprojTl : g_wqkvTl;
    const int R = 1024;
    const int c0 = blockIdx.x * 32, r0 = blockIdx.y * 32;
    const int tx = threadIdx.x, ty = threadIdx.y;  // 32 x 8
#pragma unroll
    for (int i = 0; i < 32; i += 8)
        t[ty + i][tx] = in[(size_t)(r0 + ty + i) * C + c0 + tx];
    __syncthreads();
#pragma unroll
    for (int i = 0; i < 32; i += 8) {
        const float v = t[tx][ty + i];
        const uint32_t hp = packbf(v, 0.f);
        const uint32_t lp = packbf(v - bf_lo(hp), 0.f);
        const size_t off = (size_t)(c0 + ty + i) * R + r0 + tx;
        oh[off] = (uint16_t)hp;
        ol[off] = (uint16_t)lp;
    }
}

// ---------------------------------------------------------------------------
// Split-bf16 GEMM: C[128x128] = A[m,1024] x BT[n,1024]^T (3 mma per k16).
// mode 0: A = x planes, B = wqkvT planes; scatter -> q/k/v planes (+bias, q/8)
// mode 1: A = o planes, B = wprojT planes; fp32 out (+bias)
// 256 threads, 8 warps 2x4, warp tile 64x32. BK=32 elems, double-buffered.
// Smem buffer stride 40960B: AH@0, AL@10240, BH@20480, BL@30720; rows 80B.
// ---------------------------------------------------------------------------
#define GEMM_SMEM_BYTES (2 * 40960)

__global__ __launch_bounds__(256) void gemm_bf16(const float* __restrict__ bias,
                                                 float* __restrict__ Cout, int mode) {
    extern __shared__ __align__(16) char smc[];
    const uint32_t sb = smem_u32(smc);

    const uint16_t* Ah = mode ? g_oh : g_xh;
    const uint16_t* Al = mode ? g_ol : g_xl;
    const uint16_t* Bh = mode ? g_wprojTh : g_wqkvTh;
    const uint16_t* Bl = mode ? g_wprojTl : g_wqkvTl;

    const int m0 = blockIdx.y * 128;
    const int n0 = blockIdx.x * 128;
    const int tid = threadIdx.x;
    const int warp = tid >> 5, lane = tid & 31;
    const int g = lane >> 2, tig = lane & 3;
    const int wm = (warp >> 2) * 64;
    const int wn = (warp & 3) * 32;

    // ldmatrix lane addr components
    const int rA = lane & 15, kA = (lane >> 4) << 4;
    const int rB = ((lane >> 4) << 3) + (lane & 7), kB = ((lane >> 3) & 1) << 4;

    float c[4][4][4];
#pragma unroll
    for (int i = 0; i < 4; i++)
#pragma unroll
        for (int j = 0; j < 4; j++)
#pragma unroll
            for (int r = 0; r < 4; r++) c[i][j][r] = 0.f;

    auto prefetch = [&](int buf, int kc) {
        const uint32_t base = sb + buf * 40960;
#pragma unroll
        for (int i = 0; i < 2; i++) {
            const int idx = tid + i * 256;          // 0..511
            const int row = idx >> 2, cc = idx & 3;
            const uint32_t so = (uint32_t)(row * 80 + cc * 16);
            const size_t goA = (size_t)(m0 + row) * 1024 + kc * 32 + cc * 8;
            const size_t goB = (size_t)(n0 + row) * 1024 + kc * 32 + cc * 8;
            cp_async16(base + so,         Ah + goA);
            cp_async16(base + 10240 + so, Al + goA);
            cp_async16(base + 20480 + so, Bh + goB);
            cp_async16(base + 30720 + so, Bl + goB);
        }
        cp_commit();
    };

    prefetch(0, 0);

    for (int kc = 0; kc < 32; kc++) {
        const int p = kc & 1;
        cp_wait0();
        __syncthreads();
        if (kc < 31) prefetch(p ^ 1, kc + 1);

        const uint32_t bufb = sb + p * 40960;
#pragma unroll
        for (int ks = 0; ks < 2; ks++) {
            const uint32_t ko = ks * 32;
            uint32_t ah[4][4], al[4][4], bh[2][4], bl[2][4];
#pragma unroll
            for (int mt = 0; mt < 4; mt++) {
                const uint32_t ao = (uint32_t)((wm + rA + mt * 16) * 80) + kA + ko;
                ldsm_x4(ah[mt][0], ah[mt][1], ah[mt][2], ah[mt][3], bufb + ao);
                ldsm_x4(al[mt][0], al[mt][1], al[mt][2], al[mt][3], bufb + 10240 + ao);
            }
#pragma unroll
            for (int ntp = 0; ntp < 2; ntp++) {
                const uint32_t bo = (uint32_t)((wn + rB + ntp * 16) * 80) + kB + ko;
                ldsm_x4(bh[ntp][0], bh[ntp][1], bh[ntp][2], bh[ntp][3], bufb + 20480 + bo);
                ldsm_x4(bl[ntp][0], bl[ntp][1], bl[ntp][2], bl[ntp][3], bufb + 30720 + bo);
            }
#pragma unroll
            for (int mt = 0; mt < 4; mt++)
#pragma unroll
                for (int ntp = 0; ntp < 2; ntp++)
#pragma unroll
                    for (int hf = 0; hf < 2; hf++) {
                        const int nt = ntp * 2 + hf;
                        const uint32_t kb0 = bh[ntp][2 * hf], kb1 = bh[ntp][2 * hf + 1];
                        const uint32_t lb0 = bl[ntp][2 * hf], lb1 = bl[ntp][2 * hf + 1];
                        mma_bf16(c[mt][nt][0], c[mt][nt][1], c[mt][nt][2], c[mt][nt][3],
                                 ah[mt][0], ah[mt][1], ah[mt][2], ah[mt][3], lb0, lb1);
                        mma_bf16(c[mt][nt][0], c[mt][nt][1], c[mt][nt][2], c[mt][nt][3],
                                 al[mt][0], al[mt][1], al[mt][2], al[mt][3], kb0, kb1);
                        mma_bf16(c[mt][nt][0], c[mt][nt][1], c[mt][nt][2], c[mt][nt][3],
                                 ah[mt][0], ah[mt][1], ah[mt][2], ah[mt][3], kb0, kb1);
                    }
        }
        __syncthreads();
    }

    // ---- epilogue ----
#pragma unroll
    for (int mt = 0; mt < 4; mt++) {
#pragma unroll
        for (int nt = 0; nt < 4; nt++) {
            const int rowA = m0 + wm + mt * 16 + g;
            const int rowB = rowA + 8;
            const int n = n0 + wn + nt * 8 + 2 * tig;
            const float b0 = bias[n], b1 = bias[n + 1];
            float v0 = c[mt][nt][0] + b0, v1 = c[mt][nt][1] + b1;
            float v2 = c[mt][nt][2] + b0, v3 = c[mt][nt][3] + b1;
            if (mode == 1) {
                *(float2*)(Cout + (size_t)rowA * 1024 + n) = make_float2(v0, v1);
                *(float2*)(Cout + (size_t)rowB * 1024 + n) = make_float2(v2, v3);
            } else {
                const int which = n >> 10;
                const int nm = n & 1023;
                const int h = nm >> 6, dd = nm & 63;
                uint16_t* dsth = (which == 0) ? g_qh : (which == 1) ? g_kh : g_vh;
                uint16_t* dstl = (which == 0) ? g_ql : (which == 1) ? g_kl : g_vl;
                const float sc = (which == 0) ? 0.125f : 1.f;
                v0 *= sc; v1 *= sc; v2 *= sc; v3 *= sc;
                const int bA = rowA >> 10, sAr = rowA & 1023;
                const int bB = rowB >> 10, sBr = rowB & 1023;
                const size_t offA =
                    (((size_t)(bA * NB_HEADS + h) * SEQ) + sAr) * HEAD_DIM + dd;
                const size_t offB =
                    (((size_t)(bB * NB_HEADS + h) * SEQ) + sBr) * HEAD_DIM + dd;
                uint32_t hh = packbf(v0, v1);
                *(uint32_t*)&dsth[offA] = hh;
                *(uint32_t*)&dstl[offA] = packbf(v0 - bf_lo(hh), v1 - bf_hi(hh));
                hh = packbf(v2, v3);
                *(uint32_t*)&dsth[offB] = hh;
                *(uint32_t*)&dstl[offB] = packbf(v2 - bf_lo(hh), v3 - bf_hi(hh));
            }
        }
    }
}

// ---------------------------------------------------------------------------
// Split-bf16 flash attention. Operands arrive pre-split via cp.async.
// Block = (128 queries) x (b,h). 256 threads / 8 warps, warp owns 16 q-rows.
// Smem rows 144 B. QH@0, QL@18432, PH@36864, PL@55296, KV@73728 (2x36864).
// ---------------------------------------------------------------------------
#define RB 144
#define OB_QH 0
#define OB_QL 18432
#define OB_PH 36864
#define OB_PL 55296
#define OB_KV 73728
#define ATTN_SMEM_BYTES (OB_KV + 2 * 36864)

__global__ __launch_bounds__(256, 1) void attn_mma() {
    extern __shared__ __align__(16) char smc[];
    const uint32_t sb = smem_u32(smc);

    const int tid = threadIdx.x;
    const int warp = tid >> 5, lane = tid & 31;
    const int g = lane >> 2, tig = lane & 3;
    const int wb = warp * 16;

    const int q0 = blockIdx.x * 128;
    const int h = blockIdx.y, b = blockIdx.z;
    const size_t bh = (size_t)(b * NB_HEADS + h) * SEQ * HEAD_DIM;

    auto issue_tile = [&](int k0, int p) {
        const uint32_t kvb = sb + OB_KV + p * 36864;
#pragma unroll
        for (int i = 0; i < 2; i++) {
            const int idx = tid + i * 256;          // 0..511
            const int row = idx >> 3, cc = idx & 7;
            const uint32_t so = (uint32_t)(row * RB + cc * 16);
            const size_t go = bh + (size_t)(k0 + row) * 64 + cc * 8;
            cp_async16(kvb + so,          g_kh + go);
            cp_async16(kvb + 9216 + so,   g_kl + go);
            cp_async16(kvb + 18432 + so,  g_vh + go);
            cp_async16(kvb + 27648 + so,  g_vl + go);
        }
        cp_commit();
    };

    // ---- prologue: Q hi/lo + tile 0 ----
    {
#pragma unroll
        for (int i = 0; i < 4; i++) {
            const int idx = tid + i * 256;          // 0..1023
            const int row = idx >> 3, cc = idx & 7;
            const uint32_t so = (uint32_t)(row * RB + cc * 16);
            const size_t go = bh + (size_t)(q0 + row) * 64 + cc * 8;
            cp_async16(sb + OB_QH + so, g_qh + go);
            cp_async16(sb + OB_QL + so, g_ql + go);
        }
        cp_commit();
        issue_tile(0, 0);
    }

    // ldmatrix lane addr components
    const int rA = lane & 15, kA = (lane >> 4) << 4;
    const int rK = ((lane >> 4) << 3) + (lane & 7), kK = ((lane >> 3) & 1) << 4;
    const int rV = lane & 15, dV = (lane >> 4) << 4;

    const uint32_t aQH = sb + OB_QH + (wb + rA) * RB + kA;
    const uint32_t aQL = sb + OB_QL + (wb + rA) * RB + kA;
    const uint32_t aPH = sb + OB_PH + (wb + rA) * RB + kA;
    const uint32_t aPL = sb + OB_PL + (wb + rA) * RB + kA;

    float o[8][4];
#pragma unroll
    for (int nt = 0; nt < 8; nt++)
#pragma unroll
        for (int r = 0; r < 4; r++) o[nt][r] = 0.f;
    float m0 = -1e30f, m1 = -1e30f, l0 = 0.f, l1 = 0.f;

    for (int kb0 = 0; kb0 < 16; kb0++) {
        const int p = kb0 & 1;
        cp_wait0();
        __syncthreads();   // all warps done reading buffer p^1 (prev iter)
        if (kb0 < 15) issue_tile((kb0 + 1) * 64, p ^ 1);

        const uint32_t kvb = sb + OB_KV + p * 36864;
        const uint32_t aKH = kvb + rK * RB + kK;
        const uint32_t aKL = kvb + 9216 + rK * RB + kK;
        const uint32_t aVH = kvb + 18432 + rV * RB + dV;
        const uint32_t aVL = kvb + 27648 + rV * RB + dV;

        // ---- S = Q K^T : 3 bf16 mma per k16 ----
        float s[8][4];
#pragma unroll
        for (int nt = 0; nt < 8; nt++)
#pragma unroll
            for (int r = 0; r < 4; r++) s[nt][r] = 0.f;

#pragma unroll
        for (int ks = 0; ks < 4; ks++) {
            const uint32_t ko = ks * 32;
            uint32_t ah0, ah1, ah2, ah3, al0, al1, al2, al3;
            ldsm_x4(ah0, ah1, ah2, ah3, aQH + ko);
            ldsm_x4(al0, al1, al2, al3, aQL + ko);
#pragma unroll
            for (int ntp = 0; ntp < 4; ntp++) {
                const uint32_t no = (uint32_t)(ntp * 16 * RB) + ko;
                uint32_t kh0, kh1, kh2, kh3, kl0, kl1, kl2, kl3;
                ldsm_x4(kh0, kh1, kh2, kh3, aKH + no);
                ldsm_x4(kl0, kl1, kl2, kl3, aKL + no);
                const int n0t = 2 * ntp, n1t = 2 * ntp + 1;
                mma_bf16(s[n0t][0], s[n0t][1], s[n0t][2], s[n0t][3],
                         ah0, ah1, ah2, ah3, kl0, kl1);
                mma_bf16(s[n0t][0], s[n0t][1], s[n0t][2], s[n0t][3],
                         al0, al1, al2, al3, kh0, kh1);
                mma_bf16(s[n0t][0], s[n0t][1], s[n0t][2], s[n0t][3],
                         ah0, ah1, ah2, ah3, kh0, kh1);
                mma_bf16(s[n1t][0], s[n1t][1], s[n1t][2], s[n1t][3],
                         ah0, ah1, ah2, ah3, kl2, kl3);
                mma_bf16(s[n1t][0], s[n1t][1], s[n1t][2], s[n1t][3],
                         al0, al1, al2, al3, kh2, kh3);
                mma_bf16(s[n1t][0], s[n1t][1], s[n1t][2], s[n1t][3],
                         ah0, ah1, ah2, ah3, kh2, kh3);
            }
        }

        // ---- fragment online softmax ----
        float rmax0 = -1e30f, rmax1 = -1e30f;
#pragma unroll
        for (int nt = 0; nt < 8; nt++) {
            rmax0 = fmaxf(rmax0, fmaxf(s[nt][0], s[nt][1]));
            rmax1 = fmaxf(rmax1, fmaxf(s[nt][2], s[nt][3]));
        }
        rmax0 = fmaxf(rmax0, __shfl_xor_sync(0xffffffffu, rmax0, 1));
        rmax0 = fmaxf(rmax0, __shfl_xor_sync(0xffffffffu, rmax0, 2));
        rmax1 = fmaxf(rmax1, __shfl_xor_sync(0xffffffffu, rmax1, 1));
        rmax1 = fmaxf(rmax1, __shfl_xor_sync(0xffffffffu, rmax1, 2));

        const float mn0 = fmaxf(m0, rmax0), mn1 = fmaxf(m1, rmax1);
        const float corr0 = __expf(m0 - mn0), corr1 = __expf(m1 - mn1);
        m0 = mn0; m1 = mn1;

        float ls0 = 0.f, ls1 = 0.f;
#pragma unroll
        for (int nt = 0; nt < 8; nt++) {
            s[nt][0] = __expf(s[nt][0] - mn0);
            s[nt][1] = __expf(s[nt][1] - mn0);
            s[nt][2] = __expf(s[nt][2] - mn1);
            s[nt][3] = __expf(s[nt][3] - mn1);
            ls0 += s[nt][0] + s[nt][1];
            ls1 += s[nt][2] + s[nt][3];
        }
        ls0 += __shfl_xor_sync(0xffffffffu, ls0, 1);
        ls0 += __shfl_xor_sync(0xffffffffu, ls0, 2);
        ls1 += __shfl_xor_sync(0xffffffffu, ls1, 1);
        ls1 += __shfl_xor_sync(0xffffffffu, ls1, 2);
        l0 = l0 * corr0 + ls0;
        l1 = l1 * corr1 + ls1;

        // ---- stage P as bf16 hi/lo (warp-private rows) ----
#pragma unroll
        for (int nt = 0; nt < 8; nt++) {
            const int cby = nt * 16 + tig * 4;
            uint32_t ph = packbf(s[nt][0], s[nt][1]);
            *(uint32_t*)(smc + OB_PH + (wb + g) * RB + cby) = ph;
            *(uint32_t*)(smc + OB_PL + (wb + g) * RB + cby) =
                packbf(s[nt][0] - bf_lo(ph), s[nt][1] - bf_hi(ph));
            ph = packbf(s[nt][2], s[nt][3]);
            *(uint32_t*)(smc + OB_PH + (wb + g + 8) * RB + cby) = ph;
            *(uint32_t*)(smc + OB_PL + (wb + g + 8) * RB + cby) =
                packbf(s[nt][2] - bf_lo(ph), s[nt][3] - bf_hi(ph));
        }
        __syncwarp();

        // rescale O
#pragma unroll
        for (int nt = 0; nt < 8; nt++) {
            o[nt][0] *= corr0; o[nt][1] *= corr0;
            o[nt][2] *= corr1; o[nt][3] *= corr1;
        }

        // ---- O += P V : 3 bf16 mma per k16, V via ldmatrix.trans ----
#pragma unroll
        for (int ks = 0; ks < 4; ks++) {
            const uint32_t ko = ks * 32;
            uint32_t ph0, ph1, ph2, ph3, pl0, pl1, pl2, pl3;
            ldsm_x4(ph0, ph1, ph2, ph3, aPH + ko);
            ldsm_x4(pl0, pl1, pl2, pl3, aPL + ko);
#pragma unroll
            for (int ntp = 0; ntp < 4; ntp++) {
                const uint32_t vo = (uint32_t)(ks * 16 * RB) + ntp * 32;
                uint32_t vh0, vh1, vh2, vh3, vl0, vl1, vl2, vl3;
                ldsm_x4_t(vh0, vh1, vh2, vh3, aVH + vo);
                ldsm_x4_t(vl0, vl1, vl2, vl3, aVL + vo);
                const int n0t = 2 * ntp, n1t = 2 * ntp + 1;
                mma_bf16(o[n0t][0], o[n0t][1], o[n0t][2], o[n0t][3],
                         ph0, ph1, ph2, ph3, vl0, vl1);
                mma_bf16(o[n0t][0], o[n0t][1], o[n0t][2], o[n0t][3],
                         pl0, pl1, pl2, pl3, vh0, vh1);
                mma_bf16(o[n0t][0], o[n0t][1], o[n0t][2], o[n0t][3],
                         ph0, ph1, ph2, ph3, vh0, vh1);
                mma_bf16(o[n1t][0], o[n1t][1], o[n1t][2], o[n1t][3],
                         ph0, ph1, ph2, ph3, vl2, vl3);
                mma_bf16(o[n1t][0], o[n1t][1], o[n1t][2], o[n1t][3],
                         pl0, pl1, pl2, pl3, vh2, vh3);
                mma_bf16(o[n1t][0], o[n1t][1], o[n1t][2], o[n1t][3],
                         ph0, ph1, ph2, ph3, vh2, vh3);
            }
        }
    }

    // ---- epilogue: normalize, split, store o hi/lo planes ----
    const float il0 = 1.f / l0, il1 = 1.f / l1;
    const int r0 = q0 + wb + g, r1 = r0 + 8;
#pragma unroll
    for (int nt = 0; nt < 8; nt++) {
        const int col = h * HEAD_DIM + nt * 8 + 2 * tig;
        const size_t offA = ((size_t)b * SEQ + r0) * DMODEL + col;
        const size_t offB = ((size_t)b * SEQ + r1) * DMODEL + col;
        float v0 = o[nt][0] * il0, v1 = o[nt][1] * il0;
        float v2 = o[nt][2] * il1, v3 = o[nt][3] * il1;
        uint32_t hh = packbf(v0, v1);
        *(uint32_t*)&g_oh[offA] = hh;
        *(uint32_t*)&g_ol[offA] = packbf(v0 - bf_lo(hh), v1 - bf_hi(hh));
        hh = packbf(v2, v3);
        *(uint32_t*)&g_oh[offB] = hh;
        *(uint32_t*)&g_ol[offB] = packbf(v2 - bf_lo(hh), v3 - bf_hi(hh));
    }
}

// ---------------------------------------------------------------------------

extern "C" void kernel_launch(void* const* d_in, const int* in_sizes, int n_in,
                              void* d_out, int out_size) {
    (void)in_sizes; (void)n_in; (void)out_size;
    const float* x      = (const float*)d_in[0];
    const float* w_qkv  = (const float*)d_in[1];
    const float* b_qkv  = (const float*)d_in[2];
    const float* w_proj = (const float*)d_in[3];
    const float* b_proj = (const float*)d_in[4];
    float* out = (float*)d_out;

    cudaFuncSetAttribute(gemm_bf16, cudaFuncAttributeMaxDynamicSharedMemorySize,
                         GEMM_SMEM_BYTES);
    cudaFuncSetAttribute(attn_mma, cudaFuncAttributeMaxDynamicSharedMemorySize,
                         ATTN_SMEM_BYTES);

    split_fp32<<<(NTOK * DMODEL / 4 + 255) / 256, 256>>>(x, NTOK * DMODEL / 4);
    transpose_split<<<dim3(96, 32), dim3(32, 8)>>>(w_qkv, 3072, 0);
    transpose_split<<<dim3(32, 32), dim3(32, 8)>>>(w_proj, 1024, 1);

    gemm_bf16<<<dim3(24, 64), 256, GEMM_SMEM_BYTES>>>(b_qkv, nullptr, 0);

    attn_mma<<<dim3(SEQ / 128, NB_HEADS, BATCH), 256, ATTN_SMEM_BYTES>>>();

    gemm_bf16<<<dim3(8, 64), 256, GEMM_SMEM_BYTES>>>(b_proj, out, 1);
}

// round 17
// speedup vs baseline: 1.1242x; 1.1242x over previous
#include <cuda_runtime.h>
#include <cuda.h>
#include <cstdint>
#include <math.h>

// ---------------------------------------------------------------------------
// ViT MHA B=8, S=1024, D=1024, H=16, hd=64 (fp32 in/out).
// R15 = R13 resubmitted (two consecutive broker/container-infra failures; the
//       kernel has never executed). Split-bf16 planes everywhere + gemm
//       occupancy fix: __launch_bounds__(256,2) and low-live-register loop.
// ---------------------------------------------------------------------------

#define NB_HEADS 16
#define HEAD_DIM 64
#define SEQ 1024
#define BATCH 8
#define DMODEL 1024
#define NTOK (BATCH * SEQ)                     // 8192

// bf16 hi/lo planes (uint16_t storage), 16B-aligned for cp.async/uint2
__device__ __align__(16) uint16_t g_xh[(size_t)NTOK * DMODEL];
__device__ __align__(16) uint16_t g_xl[(size_t)NTOK * DMODEL];
__device__ __align__(16) uint16_t g_wqkvTh[(size_t)3072 * 1024];
__device__ __align__(16) uint16_t g_wqkvTl[(size_t)3072 * 1024];
__device__ __align__(16) uint16_t g_wprojTh[(size_t)1024 * 1024];
__device__ __align__(16) uint16_t g_wprojTl[(size_t)1024 * 1024];
__device__ __align__(16) uint16_t g_qh[(size_t)NTOK * DMODEL];
__device__ __align__(16) uint16_t g_ql[(size_t)NTOK * DMODEL];
__device__ __align__(16) uint16_t g_kh[(size_t)NTOK * DMODEL];
__device__ __align__(16) uint16_t g_kl[(size_t)NTOK * DMODEL];
__device__ __align__(16) uint16_t g_vh[(size_t)NTOK * DMODEL];
__device__ __align__(16) uint16_t g_vl[(size_t)NTOK * DMODEL];
__device__ __align__(16) uint16_t g_oh[(size_t)NTOK * DMODEL];
__device__ __align__(16) uint16_t g_ol[(size_t)NTOK * DMODEL];

// ------------------------------ helpers ------------------------------------
__device__ __forceinline__ uint32_t smem_u32(const void* p) {
    uint32_t a;
    asm("{ .reg .u64 t; cvta.to.shared.u64 t, %1; cvt.u32.u64 %0, t; }"
        : "=r"(a) : "l"(p));
    return a;
}

__device__ __forceinline__ uint32_t packbf(float lo, float hi) {
    uint32_t r;
    asm("cvt.rn.bf16x2.f32 %0, %1, %2;" : "=r"(r) : "f"(hi), "f"(lo));
    return r;
}
__device__ __forceinline__ float bf_lo(uint32_t u) { return __uint_as_float(u << 16); }
__device__ __forceinline__ float bf_hi(uint32_t u) { return __uint_as_float(u & 0xffff0000u); }

__device__ __forceinline__ void cp_async16(uint32_t dst, const void* src) {
    asm volatile("cp.async.ca.shared.global [%0], [%1], 16;"
                 :: "r"(dst), "l"(src) : "memory");
}
__device__ __forceinline__ void cp_commit() {
    asm volatile("cp.async.commit_group;" ::: "memory");
}
__device__ __forceinline__ void cp_wait0() {
    asm volatile("cp.async.wait_group 0;" ::: "memory");
}

__device__ __forceinline__ void mma_bf16(float& c0, float& c1, float& c2, float& c3,
                                         uint32_t a0, uint32_t a1, uint32_t a2,
                                         uint32_t a3, uint32_t b0, uint32_t b1) {
    asm volatile(
        "mma.sync.aligned.m16n8k16.row.col.f32.bf16.bf16.f32 "
        "{%0,%1,%2,%3}, {%4,%5,%6,%7}, {%8,%9}, {%0,%1,%2,%3};"
        : "+f"(c0), "+f"(c1), "+f"(c2), "+f"(c3)
        : "r"(a0), "r"(a1), "r"(a2), "r"(a3), "r"(b0), "r"(b1));
}

__device__ __forceinline__ void ldsm_x4(uint32_t& r0, uint32_t& r1,
                                        uint32_t& r2, uint32_t& r3, uint32_t a) {
    asm volatile("ldmatrix.sync.aligned.m8n8.x4.shared.b16 {%0,%1,%2,%3}, [%4];"
                 : "=r"(r0), "=r"(r1), "=r"(r2), "=r"(r3) : "r"(a));
}
__device__ __forceinline__ void ldsm_x4_t(uint32_t& r0, uint32_t& r1,
                                          uint32_t& r2, uint32_t& r3, uint32_t a) {
    asm volatile("ldmatrix.sync.aligned.m8n8.x4.trans.shared.b16 {%0,%1,%2,%3}, [%4];"
                 : "=r"(r0), "=r"(r1), "=r"(r2), "=r"(r3) : "r"(a));
}

// ---------------------------------------------------------------------------
// Prep: split x (fp32) -> g_xh / g_xl.
// ---------------------------------------------------------------------------
__global__ __launch_bounds__(256) void split_fp32(const float* __restrict__ in,
                                                  int n4) {
    const int i = blockIdx.x * 256 + threadIdx.x;
    if (i < n4) {
        const float4 v = ((const float4*)in)[i];
        const uint32_t h01 = packbf(v.x, v.y), h23 = packbf(v.z, v.w);
        const uint32_t l01 = packbf(v.x - bf_lo(h01), v.y - bf_hi(h01));
        const uint32_t l23 = packbf(v.z - bf_lo(h23), v.w - bf_hi(h23));
        ((uint2*)g_xh)[i] = make_uint2(h01, h23);
        ((uint2*)g_xl)[i] = make_uint2(l01, l23);
    }
}

// ---------------------------------------------------------------------------
// Prep: transpose + split weights. in [1024][C] fp32 -> [C][1024] hi/lo.
// ---------------------------------------------------------------------------
__global__ __launch_bounds__(256) void transpose_split(const float* __restrict__ in,
                                                       int C, int which) {
    __shared__ float t[32][33];
    uint16_t* oh = which ? g_wprojTh : g_wqkvTh;
    uint16_t* ol = which ? g_wprojTl : g_wqkvTl;
    const int R = 1024;
    const int c0 = blockIdx.x * 32, r0 = blockIdx.y * 32;
    const int tx = threadIdx.x, ty = threadIdx.y;  // 32 x 8
#pragma unroll
    for (int i = 0; i < 32; i += 8)
        t[ty + i][tx] = in[(size_t)(r0 + ty + i) * C + c0 + tx];
    __syncthreads();
#pragma unroll
    for (int i = 0; i < 32; i += 8) {
        const float v = t[tx][ty + i];
        const uint32_t hp = packbf(v, 0.f);
        const uint32_t lp = packbf(v - bf_lo(hp), 0.f);
        const size_t off = (size_t)(c0 + ty + i) * R + r0 + tx;
        oh[off] = (uint16_t)hp;
        ol[off] = (uint16_t)lp;
    }
}

// ---------------------------------------------------------------------------
// Split-bf16 GEMM: C[128x128] = A[m,1024] x BT[n,1024]^T (3 mma per k16).
// __launch_bounds__(256, 2): <=128 regs -> 2 CTAs/SM (16 warps).
// Inner loop keeps live fragments small: B per ks, A per mt.
// ---------------------------------------------------------------------------
#define GEMM_SMEM_BYTES (2 * 40960)

__global__ __launch_bounds__(256, 2) void gemm_bf16(const float* __restrict__ bias,
                                                    float* __restrict__ Cout, int mode) {
    extern __shared__ __align__(16) char smc[];
    const uint32_t sb = smem_u32(smc);

    const uint16_t* Ah = mode ? g_oh : g_xh;
    const uint16_t* Al = mode ? g_ol : g_xl;
    const uint16_t* Bh = mode ? g_wprojTh : g_wqkvTh;
    const uint16_t* Bl = mode ? g_wprojTl : g_wqkvTl;

    const int m0 = blockIdx.y * 128;
    const int n0 = blockIdx.x * 128;
    const int tid = threadIdx.x;
    const int warp = tid >> 5, lane = tid & 31;
    const int g = lane >> 2, tig = lane & 3;
    const int wm = (warp >> 2) * 64;
    const int wn = (warp & 3) * 32;

    // ldmatrix lane addr components
    const int rA = lane & 15, kA = (lane >> 4) << 4;
    const int rB = ((lane >> 4) << 3) + (lane & 7), kB = ((lane >> 3) & 1) << 4;

    float c[4][4][4];
#pragma unroll
    for (int i = 0; i < 4; i++)
#pragma unroll
        for (int j = 0; j < 4; j++)
#pragma unroll
            for (int r = 0; r < 4; r++) c[i][j][r] = 0.f;

    auto prefetch = [&](int buf, int kc) {
        const uint32_t base = sb + buf * 40960;
#pragma unroll
        for (int i = 0; i < 2; i++) {
            const int idx = tid + i * 256;          // 0..511
            const int row = idx >> 2, cc = idx & 3;
            const uint32_t so = (uint32_t)(row * 80 + cc * 16);
            const size_t goA = (size_t)(m0 + row) * 1024 + kc * 32 + cc * 8;
            const size_t goB = (size_t)(n0 + row) * 1024 + kc * 32 + cc * 8;
            cp_async16(base + so,         Ah + goA);
            cp_async16(base + 10240 + so, Al + goA);
            cp_async16(base + 20480 + so, Bh + goB);
            cp_async16(base + 30720 + so, Bl + goB);
        }
        cp_commit();
    };

    prefetch(0, 0);

    for (int kc = 0; kc < 32; kc++) {
        const int p = kc & 1;
        cp_wait0();
        __syncthreads();
        if (kc < 31) prefetch(p ^ 1, kc + 1);

        const uint32_t bufb = sb + p * 40960;
#pragma unroll
        for (int ks = 0; ks < 2; ks++) {
            const uint32_t ko = ks * 32;
            uint32_t bh[2][4], bl[2][4];
#pragma unroll
            for (int ntp = 0; ntp < 2; ntp++) {
                const uint32_t bo = (uint32_t)((wn + rB + ntp * 16) * 80) + kB + ko;
                ldsm_x4(bh[ntp][0], bh[ntp][1], bh[ntp][2], bh[ntp][3], bufb + 20480 + bo);
                ldsm_x4(bl[ntp][0], bl[ntp][1], bl[ntp][2], bl[ntp][3], bufb + 30720 + bo);
            }
#pragma unroll
            for (int mt = 0; mt < 4; mt++) {
                const uint32_t ao = (uint32_t)((wm + rA + mt * 16) * 80) + kA + ko;
                uint32_t a0, a1, a2, a3, l0r, l1r, l2r, l3r;
                ldsm_x4(a0, a1, a2, a3, bufb + ao);
                ldsm_x4(l0r, l1r, l2r, l3r, bufb + 10240 + ao);
#pragma unroll
                for (int ntp = 0; ntp < 2; ntp++)
#pragma unroll
                    for (int hf = 0; hf < 2; hf++) {
                        const int nt = ntp * 2 + hf;
                        const uint32_t kb0 = bh[ntp][2 * hf], kb1 = bh[ntp][2 * hf + 1];
                        const uint32_t lb0 = bl[ntp][2 * hf], lb1 = bl[ntp][2 * hf + 1];
                        mma_bf16(c[mt][nt][0], c[mt][nt][1], c[mt][nt][2], c[mt][nt][3],
                                 a0, a1, a2, a3, lb0, lb1);
                        mma_bf16(c[mt][nt][0], c[mt][nt][1], c[mt][nt][2], c[mt][nt][3],
                                 l0r, l1r, l2r, l3r, kb0, kb1);
                        mma_bf16(c[mt][nt][0], c[mt][nt][1], c[mt][nt][2], c[mt][nt][3],
                                 a0, a1, a2, a3, kb0, kb1);
                    }
            }
        }
        __syncthreads();
    }

    // ---- epilogue ----
#pragma unroll
    for (int mt = 0; mt < 4; mt++) {
#pragma unroll
        for (int nt = 0; nt < 4; nt++) {
            const int rowA = m0 + wm + mt * 16 + g;
            const int rowB = rowA + 8;
            const int n = n0 + wn + nt * 8 + 2 * tig;
            const float b0 = bias[n], b1 = bias[n + 1];
            float v0 = c[mt][nt][0] + b0, v1 = c[mt][nt][1] + b1;
            float v2 = c[mt][nt][2] + b0, v3 = c[mt][nt][3] + b1;
            if (mode == 1) {
                *(float2*)(Cout + (size_t)rowA * 1024 + n) = make_float2(v0, v1);
                *(float2*)(Cout + (size_t)rowB * 1024 + n) = make_float2(v2, v3);
            } else {
                const int which = n >> 10;
                const int nm = n & 1023;
                const int h = nm >> 6, dd = nm & 63;
                uint16_t* dsth = (which == 0) ? g_qh : (which == 1) ? g_kh : g_vh;
                uint16_t* dstl = (which == 0) ? g_ql : (which == 1) ? g_kl : g_vl;
                const float sc = (which == 0) ? 0.125f : 1.f;
                v0 *= sc; v1 *= sc; v2 *= sc; v3 *= sc;
                const int bA = rowA >> 10, sAr = rowA & 1023;
                const int bB = rowB >> 10, sBr = rowB & 1023;
                const size_t offA =
                    (((size_t)(bA * NB_HEADS + h) * SEQ) + sAr) * HEAD_DIM + dd;
                const size_t offB =
                    (((size_t)(bB * NB_HEADS + h) * SEQ) + sBr) * HEAD_DIM + dd;
                uint32_t hh = packbf(v0, v1);
                *(uint32_t*)&dsth[offA] = hh;
                *(uint32_t*)&dstl[offA] = packbf(v0 - bf_lo(hh), v1 - bf_hi(hh));
                hh = packbf(v2, v3);
                *(uint32_t*)&dsth[offB] = hh;
                *(uint32_t*)&dstl[offB] = packbf(v2 - bf_lo(hh), v3 - bf_hi(hh));
            }
        }
    }
}

// ---------------------------------------------------------------------------
// Split-bf16 flash attention (unchanged from R11 — measured ~310 us).
// ---------------------------------------------------------------------------
#define RB 144
#define OB_QH 0
#define OB_QL 18432
#define OB_PH 36864
#define OB_PL 55296
#define OB_KV 73728
#define ATTN_SMEM_BYTES (OB_KV + 2 * 36864)

__global__ __launch_bounds__(256, 1) void attn_mma() {
    extern __shared__ __align__(16) char smc[];
    const uint32_t sb = smem_u32(smc);

    const int tid = threadIdx.x;
    const int warp = tid >> 5, lane = tid & 31;
    const int g = lane >> 2, tig = lane & 3;
    const int wb = warp * 16;

    const int q0 = blockIdx.x * 128;
    const int h = blockIdx.y, b = blockIdx.z;
    const size_t bh = (size_t)(b * NB_HEADS + h) * SEQ * HEAD_DIM;

    auto issue_tile = [&](int k0, int p) {
        const uint32_t kvb = sb + OB_KV + p * 36864;
#pragma unroll
        for (int i = 0; i < 2; i++) {
            const int idx = tid + i * 256;
            const int row = idx >> 3, cc = idx & 7;
            const uint32_t so = (uint32_t)(row * RB + cc * 16);
            const size_t go = bh + (size_t)(k0 + row) * 64 + cc * 8;
            cp_async16(kvb + so,          g_kh + go);
            cp_async16(kvb + 9216 + so,   g_kl + go);
            cp_async16(kvb + 18432 + so,  g_vh + go);
            cp_async16(kvb + 27648 + so,  g_vl + go);
        }
        cp_commit();
    };

    // ---- prologue: Q hi/lo + tile 0 ----
    {
#pragma unroll
        for (int i = 0; i < 4; i++) {
            const int idx = tid + i * 256;
            const int row = idx >> 3, cc = idx & 7;
            const uint32_t so = (uint32_t)(row * RB + cc * 16);
            const size_t go = bh + (size_t)(q0 + row) * 64 + cc * 8;
            cp_async16(sb + OB_QH + so, g_qh + go);
            cp_async16(sb + OB_QL + so, g_ql + go);
        }
        cp_commit();
        issue_tile(0, 0);
    }

    // ldmatrix lane addr components
    const int rA = lane & 15, kA = (lane >> 4) << 4;
    const int rK = ((lane >> 4) << 3) + (lane & 7), kK = ((lane >> 3) & 1) << 4;
    const int rV = lane & 15, dV = (lane >> 4) << 4;

    const uint32_t aQH = sb + OB_QH + (wb + rA) * RB + kA;
    const uint32_t aQL = sb + OB_QL + (wb + rA) * RB + kA;
    const uint32_t aPH = sb + OB_PH + (wb + rA) * RB + kA;
    const uint32_t aPL = sb + OB_PL + (wb + rA) * RB + kA;

    float o[8][4];
#pragma unroll
    for (int nt = 0; nt < 8; nt++)
#pragma unroll
        for (int r = 0; r < 4; r++) o[nt][r] = 0.f;
    float m0 = -1e30f, m1 = -1e30f, l0 = 0.f, l1 = 0.f;

    for (int kb0 = 0; kb0 < 16; kb0++) {
        const int p = kb0 & 1;
        cp_wait0();
        __syncthreads();
        if (kb0 < 15) issue_tile((kb0 + 1) * 64, p ^ 1);

        const uint32_t kvb = sb + OB_KV + p * 36864;
        const uint32_t aKH = kvb + rK * RB + kK;
        const uint32_t aKL = kvb + 9216 + rK * RB + kK;
        const uint32_t aVH = kvb + 18432 + rV * RB + dV;
        const uint32_t aVL = kvb + 27648 + rV * RB + dV;

        // ---- S = Q K^T : 3 bf16 mma per k16 ----
        float s[8][4];
#pragma unroll
        for (int nt = 0; nt < 8; nt++)
#pragma unroll
            for (int r = 0; r < 4; r++) s[nt][r] = 0.f;

#pragma unroll
        for (int ks = 0; ks < 4; ks++) {
            const uint32_t ko = ks * 32;
            uint32_t ah0, ah1, ah2, ah3, al0, al1, al2, al3;
            ldsm_x4(ah0, ah1, ah2, ah3, aQH + ko);
            ldsm_x4(al0, al1, al2, al3, aQL + ko);
#pragma unroll
            for (int ntp = 0; ntp < 4; ntp++) {
                const uint32_t no = (uint32_t)(ntp * 16 * RB) + ko;
                uint32_t kh0, kh1, kh2, kh3, kl0, kl1, kl2, kl3;
                ldsm_x4(kh0, kh1, kh2, kh3, aKH + no);
                ldsm_x4(kl0, kl1, kl2, kl3, aKL + no);
                const int n0t = 2 * ntp, n1t = 2 * ntp + 1;
                mma_bf16(s[n0t][0], s[n0t][1], s[n0t][2], s[n0t][3],
                         ah0, ah1, ah2, ah3, kl0, kl1);
                mma_bf16(s[n0t][0], s[n0t][1], s[n0t][2], s[n0t][3],
                         al0, al1, al2, al3, kh0, kh1);
                mma_bf16(s[n0t][0], s[n0t][1], s[n0t][2], s[n0t][3],
                         ah0, ah1, ah2, ah3, kh0, kh1);
                mma_bf16(s[n1t][0], s[n1t][1], s[n1t][2], s[n1t][3],
                         ah0, ah1, ah2, ah3, kl2, kl3);
                mma_bf16(s[n1t][0], s[n1t][1], s[n1t][2], s[n1t][3],
                         al0, al1, al2, al3, kh2, kh3);
                mma_bf16(s[n1t][0], s[n1t][1], s[n1t][2], s[n1t][3],
                         ah0, ah1, ah2, ah3, kh2, kh3);
            }
        }

        // ---- fragment online softmax ----
        float rmax0 = -1e30f, rmax1 = -1e30f;
#pragma unroll
        for (int nt = 0; nt < 8; nt++) {
            rmax0 = fmaxf(rmax0, fmaxf(s[nt][0], s[nt][1]));
            rmax1 = fmaxf(rmax1, fmaxf(s[nt][2], s[nt][3]));
        }
        rmax0 = fmaxf(rmax0, __shfl_xor_sync(0xffffffffu, rmax0, 1));
        rmax0 = fmaxf(rmax0, __shfl_xor_sync(0xffffffffu, rmax0, 2));
        rmax1 = fmaxf(rmax1, __shfl_xor_sync(0xffffffffu, rmax1, 1));
        rmax1 = fmaxf(rmax1, __shfl_xor_sync(0xffffffffu, rmax1, 2));

        const float mn0 = fmaxf(m0, rmax0), mn1 = fmaxf(m1, rmax1);
        const float corr0 = __expf(m0 - mn0), corr1 = __expf(m1 - mn1);
        m0 = mn0; m1 = mn1;

        float ls0 = 0.f, ls1 = 0.f;
#pragma unroll
        for (int nt = 0; nt < 8; nt++) {
            s[nt][0] = __expf(s[nt][0] - mn0);
            s[nt][1] = __expf(s[nt][1] - mn0);
            s[nt][2] = __expf(s[nt][2] - mn1);
            s[nt][3] = __expf(s[nt][3] - mn1);
            ls0 += s[nt][0] + s[nt][1];
            ls1 += s[nt][2] + s[nt][3];
        }
        ls0 += __shfl_xor_sync(0xffffffffu, ls0, 1);
        ls0 += __shfl_xor_sync(0xffffffffu, ls0, 2);
        ls1 += __shfl_xor_sync(0xffffffffu, ls1, 1);
        ls1 += __shfl_xor_sync(0xffffffffu, ls1, 2);
        l0 = l0 * corr0 + ls0;
        l1 = l1 * corr1 + ls1;

        // ---- stage P as bf16 hi/lo (warp-private rows) ----
#pragma unroll
        for (int nt = 0; nt < 8; nt++) {
            const int cby = nt * 16 + tig * 4;
            uint32_t ph = packbf(s[nt][0], s[nt][1]);
            *(uint32_t*)(smc + OB_PH + (wb + g) * RB + cby) = ph;
            *(uint32_t*)(smc + OB_PL + (wb + g) * RB + cby) =
                packbf(s[nt][0] - bf_lo(ph), s[nt][1] - bf_hi(ph));
            ph = packbf(s[nt][2], s[nt][3]);
            *(uint32_t*)(smc + OB_PH + (wb + g + 8) * RB + cby) = ph;
            *(uint32_t*)(smc + OB_PL + (wb + g + 8) * RB + cby) =
                packbf(s[nt][2] - bf_lo(ph), s[nt][3] - bf_hi(ph));
        }
        __syncwarp();

        // rescale O
#pragma unroll
        for (int nt = 0; nt < 8; nt++) {
            o[nt][0] *= corr0; o[nt][1] *= corr0;
            o[nt][2] *= corr1; o[nt][3] *= corr1;
        }

        // ---- O += P V : 3 bf16 mma per k16, V via ldmatrix.trans ----
#pragma unroll
        for (int ks = 0; ks < 4; ks++) {
            const uint32_t ko = ks * 32;
            uint32_t ph0, ph1, ph2, ph3, pl0, pl1, pl2, pl3;
            ldsm_x4(ph0, ph1, ph2, ph3, aPH + ko);
            ldsm_x4(pl0, pl1, pl2, pl3, aPL + ko);
#pragma unroll
            for (int ntp = 0; ntp < 4; ntp++) {
                const uint32_t vo = (uint32_t)(ks * 16 * RB) + ntp * 32;
                uint32_t vh0, vh1, vh2, vh3, vl0, vl1, vl2, vl3;
                ldsm_x4_t(vh0, vh1, vh2, vh3, aVH + vo);
                ldsm_x4_t(vl0, vl1, vl2, vl3, aVL + vo);
                const int n0t = 2 * ntp, n1t = 2 * ntp + 1;
                mma_bf16(o[n0t][0], o[n0t][1], o[n0t][2], o[n0t][3],
                         ph0, ph1, ph2, ph3, vl0, vl1);
                mma_bf16(o[n0t][0], o[n0t][1], o[n0t][2], o[n0t][3],
                         pl0, pl1, pl2, pl3, vh0, vh1);
                mma_bf16(o[n0t][0], o[n0t][1], o[n0t][2], o[n0t][3],
                         ph0, ph1, ph2, ph3, vh0, vh1);
                mma_bf16(o[n1t][0], o[n1t][1], o[n1t][2], o[n1t][3],
                         ph0, ph1, ph2, ph3, vl2, vl3);
                mma_bf16(o[n1t][0], o[n1t][1], o[n1t][2], o[n1t][3],
                         pl0, pl1, pl2, pl3, vh2, vh3);
                mma_bf16(o[n1t][0], o[n1t][1], o[n1t][2], o[n1t][3],
                         ph0, ph1, ph2, ph3, vh2, vh3);
            }
        }
    }

    // ---- epilogue: normalize, split, store o hi/lo planes ----
    const float il0 = 1.f / l0, il1 = 1.f / l1;
    const int r0 = q0 + wb + g, r1 = r0 + 8;
#pragma unroll
    for (int nt = 0; nt < 8; nt++) {
        const int col = h * HEAD_DIM + nt * 8 + 2 * tig;
        const size_t offA = ((size_t)b * SEQ + r0) * DMODEL + col;
        const size_t offB = ((size_t)b * SEQ + r1) * DMODEL + col;
        float v0 = o[nt][0] * il0, v1 = o[nt][1] * il0;
        float v2 = o[nt][2] * il1, v3 = o[nt][3] * il1;
        uint32_t hh = packbf(v0, v1);
        *(uint32_t*)&g_oh[offA] = hh;
        *(uint32_t*)&g_ol[offA] = packbf(v0 - bf_lo(hh), v1 - bf_hi(hh));
        hh = packbf(v2, v3);
        *(uint32_t*)&g_oh[offB] = hh;
        *(uint32_t*)&g_ol[offB] = packbf(v2 - bf_lo(hh), v3 - bf_hi(hh));
    }
}

// ---------------------------------------------------------------------------

extern "C" void kernel_launch(void* const* d_in, const int* in_sizes, int n_in,
                              void* d_out, int out_size) {
    (void)in_sizes; (void)n_in; (void)out_size;
    const float* x      = (const float*)d_in[0];
    const float* w_qkv  = (const float*)d_in[1];
    const float* b_qkv  = (const float*)d_in[2];
    const float* w_proj = (const float*)d_in[3];
    const float* b_proj = (const float*)d_in[4];
    float* out = (float*)d_out;

    cudaFuncSetAttribute(gemm_bf16, cudaFuncAttributeMaxDynamicSharedMemorySize,
                         GEMM_SMEM_BYTES);
    cudaFuncSetAttribute(attn_mma, cudaFuncAttributeMaxDynamicSharedMemorySize,
                         ATTN_SMEM_BYTES);

    split_fp32<<<(NTOK * DMODEL / 4 + 255) / 256, 256>>>(x, NTOK * DMODEL / 4);
    transpose_split<<<dim3(96, 32), dim3(32, 8)>>>(w_qkv, 3072, 0);
    transpose_split<<<dim3(32, 32), dim3(32, 8)>>>(w_proj, 1024, 1);

    gemm_bf16<<<dim3(24, 64), 256, GEMM_SMEM_BYTES>>>(b_qkv, nullptr, 0);

    attn_mma<<<dim3(SEQ / 128, NB_HEADS, BATCH), 256, ATTN_SMEM_BYTES>>>();

    gemm_bf16<<<dim3(8, 64), 256, GEMM_SMEM_BYTES>>>(b_proj, out, 1);
}